// round 4
// baseline (speedup 1.0000x reference)
#include <cuda_runtime.h>
#include <math.h>

#define SH_C0 0.28209479177387814f
#define SH_C1 0.4886025119029199f
#define NEAR_P 0.01f
#define FAR_P 1e10f
#define LOWPASS 0.3f
#define ALPHA_MIN (1.0f/255.0f)
#define ALPHA_MAX 0.999f

#define NMAX 2048
#define TW 16
#define TH 4
#define CH 256

struct GP { float4 a; float4 b; float4 c; };
// a = (mean2d.x, mean2d.y, conA, conB)
// b = (conC, opacity, depth, unused)
// c = (colR, colG, colB, unused)
__device__ GP g_sorted[NMAX];

__global__ __launch_bounds__(1024)
void preprocess_kernel(const float* __restrict__ means3d,
                       const float* __restrict__ quats,
                       const float* __restrict__ scales,
                       const float* __restrict__ opac,
                       const float* __restrict__ sh,
                       const float* __restrict__ c2w,
                       const float* __restrict__ Km,
                       int N)
{
    __shared__ float skey[1024];
    int i = threadIdx.x;

    // viewmat = inverse of (rigid) camtoworld: Rw = R^T, tw = -R^T t
    float R00=c2w[0], R01=c2w[1], R02=c2w[2],  t0=c2w[3];
    float R10=c2w[4], R11=c2w[5], R12=c2w[6],  t1=c2w[7];
    float R20=c2w[8], R21=c2w[9], R22=c2w[10], t2=c2w[11];
    float Rw00=R00, Rw01=R10, Rw02=R20;
    float Rw10=R01, Rw11=R11, Rw12=R21;
    float Rw20=R02, Rw21=R12, Rw22=R22;
    float tw0 = -(Rw00*t0 + Rw01*t1 + Rw02*t2);
    float tw1 = -(Rw10*t0 + Rw11*t1 + Rw12*t2);
    float tw2 = -(Rw20*t0 + Rw21*t1 + Rw22*t2);
    float fx=Km[0], cx=Km[2], fy=Km[4], cy=Km[5];

    float key = INFINITY;
    float4 pa = make_float4(0,0,0,0);
    float4 pb = make_float4(0,0,0,0);
    float4 pc = make_float4(0,0,0,0);

    if (i < N) {
        float m0 = means3d[3*i+0], m1 = means3d[3*i+1], m2 = means3d[3*i+2];
        float xc = Rw00*m0 + Rw01*m1 + Rw02*m2 + tw0;
        float yc = Rw10*m0 + Rw11*m1 + Rw12*m2 + tw1;
        float zc = Rw20*m0 + Rw21*m1 + Rw22*m2 + tw2;
        bool valid = (zc > NEAR_P) && (zc < FAR_P);
        float zs = valid ? zc : 1.0f;
        float iz = 1.0f / zs;
        float m2x = fx*xc*iz + cx;
        float m2y = fy*yc*iz + cy;

        // quaternion -> rotation
        float qw=quats[4*i+0], qx=quats[4*i+1], qy=quats[4*i+2], qz=quats[4*i+3];
        float qn = rsqrtf(qw*qw + qx*qx + qy*qy + qz*qz);
        qw*=qn; qx*=qn; qy*=qn; qz*=qn;
        float Rg[3][3];
        Rg[0][0]=1.f-2.f*(qy*qy+qz*qz); Rg[0][1]=2.f*(qx*qy-qw*qz); Rg[0][2]=2.f*(qx*qz+qw*qy);
        Rg[1][0]=2.f*(qx*qy+qw*qz); Rg[1][1]=1.f-2.f*(qx*qx+qz*qz); Rg[1][2]=2.f*(qy*qz-qw*qx);
        Rg[2][0]=2.f*(qx*qz-qw*qy); Rg[2][1]=2.f*(qy*qz+qw*qx); Rg[2][2]=1.f-2.f*(qx*qx+qy*qy);

        float s0=scales[3*i+0], s1=scales[3*i+1], s2=scales[3*i+2];
        float ss0=s0*s0, ss1=s1*s1, ss2=s2*s2;

        // cov3d = (Rg * diag(s)) (Rg * diag(s))^T
        float C3[3][3];
        #pragma unroll
        for (int r=0;r<3;r++)
            #pragma unroll
            for (int c=0;c<3;c++)
                C3[r][c] = Rg[r][0]*Rg[c][0]*ss0 + Rg[r][1]*Rg[c][1]*ss1 + Rg[r][2]*Rg[c][2]*ss2;

        // cov_cam = Rw * C3 * Rw^T
        float Rwm[3][3] = {{Rw00,Rw01,Rw02},{Rw10,Rw11,Rw12},{Rw20,Rw21,Rw22}};
        float T1[3][3], Cc[3][3];
        #pragma unroll
        for (int r=0;r<3;r++)
            #pragma unroll
            for (int c=0;c<3;c++)
                T1[r][c] = Rwm[r][0]*C3[0][c] + Rwm[r][1]*C3[1][c] + Rwm[r][2]*C3[2][c];
        #pragma unroll
        for (int r=0;r<3;r++)
            #pragma unroll
            for (int c=0;c<3;c++)
                Cc[r][c] = T1[r][0]*Rwm[c][0] + T1[r][1]*Rwm[c][1] + T1[r][2]*Rwm[c][2];

        // J (2x3 projection jacobian), cov2d = J Cc J^T
        float J00 = fx*iz,  J02 = -fx*xc*iz*iz;
        float J11 = fy*iz,  J12 = -fy*yc*iz*iz;
        float v00 = J00*Cc[0][0] + J02*Cc[2][0];
        float v01 = J00*Cc[0][1] + J02*Cc[2][1];
        float v02 = J00*Cc[0][2] + J02*Cc[2][2];
        float v11 = J11*Cc[1][1] + J12*Cc[2][1];
        float v12 = J11*Cc[1][2] + J12*Cc[2][2];
        float c00 = v00*J00 + v02*J02;
        float c01 = v01*J11 + v02*J12;
        float c11 = v11*J11 + v12*J12;

        float A = c00 + LOWPASS;
        float B = c01;
        float Cq = c11 + LOWPASS;
        float det = A*Cq - B*B;
        valid = valid && (det > 0.f);
        float dets = (det > 0.f) ? det : 1.f;
        float idet = 1.f / dets;
        float conA = Cq*idet, conB = -B*idet, conC = A*idet;

        // SH degree-1 color; campos = c2w[:3,3]
        float dx = m0 - t0, dy = m1 - t1, dz = m2 - t2;
        float dn = sqrtf(dx*dx + dy*dy + dz*dz);
        float inv = 1.f / fmaxf(dn, 1e-8f);
        dx*=inv; dy*=inv; dz*=inv;
        const float* shp = sh + 12*i;
        float colr = SH_C0*shp[0] - SH_C1*dy*shp[3] + SH_C1*dz*shp[6] - SH_C1*dx*shp[9];
        float colg = SH_C0*shp[1] - SH_C1*dy*shp[4] + SH_C1*dz*shp[7] - SH_C1*dx*shp[10];
        float colb = SH_C0*shp[2] - SH_C1*dy*shp[5] + SH_C1*dz*shp[8] - SH_C1*dx*shp[11];
        colr = fmaxf(colr + 0.5f, 0.f);
        colg = fmaxf(colg + 0.5f, 0.f);
        colb = fmaxf(colb + 0.5f, 0.f);

        float opa = 1.f / (1.f + __expf(-opac[i]));
        float op = valid ? opa : 0.f;
        key = valid ? zc : INFINITY;

        pa = make_float4(m2x, m2y, conA, conB);
        pb = make_float4(conC, op, zc, 0.f);
        pc = make_float4(colr, colg, colb, 0.f);
    }

    skey[i] = key;
    __syncthreads();

    // stable O(N^2) rank (matches jnp.argsort stability; ties only at +inf where op=0)
    int rank = 0;
    float ki = key;
    #pragma unroll 4
    for (int j = 0; j < 1024; j++) {
        float kj = skey[j];
        rank += (kj < ki) || ((kj == ki) && (j < i));
    }

    if (i < N) {
        GP gp; gp.a = pa; gp.b = pb; gp.c = pc;
        g_sorted[rank] = gp;
    }
}

__global__ __launch_bounds__(TW*TH)
void rasterize_kernel(float* __restrict__ out, int N, int W, int H)
{
    __shared__ float4 sa[CH], sb[CH], sc[CH];
    int tx = threadIdx.x & (TW-1);
    int ty = threadIdx.x / TW;
    int x = blockIdx.x*TW + tx;
    int y = blockIdx.y*TH + ty;
    float pxf = x + 0.5f, pyf = y + 0.5f;

    float Tt = 1.f, cr = 0.f, cg = 0.f, cb = 0.f, acc = 0.f, ed = 0.f;

    for (int base = 0; base < N; base += CH) {
        int cnt = min(CH, N - base);
        __syncthreads();
        for (int j = threadIdx.x; j < cnt; j += TW*TH) {
            GP gp = g_sorted[base + j];
            sa[j] = gp.a; sb[j] = gp.b; sc[j] = gp.c;
        }
        __syncthreads();

        if (Tt >= 1e-5f) {
            for (int j = 0; j < cnt; j++) {
                float4 a = sa[j];
                float ddx = pxf - a.x;
                float ddy = pyf - a.y;
                float4 bq = sb[j];
                float sigma = 0.5f*(a.z*ddx*ddx + bq.x*ddy*ddy) + a.w*ddx*ddy;
                float alpha = fminf(bq.y * __expf(-sigma), ALPHA_MAX);
                if (sigma >= 0.f && alpha >= ALPHA_MIN) {
                    float w = alpha * Tt;
                    float4 cq = sc[j];
                    cr += w*cq.x; cg += w*cq.y; cb += w*cq.z;
                    acc += w; ed += w*bq.z;
                    Tt *= (1.f - alpha);
                    if (Tt < 1e-5f) break;
                }
            }
        }
        if (__syncthreads_and(Tt < 1e-5f)) break;
    }

    if (x < W && y < H) {
        int pid = y*W + x;
        float edv = ed / fmaxf(acc, 1e-10f);
        float4* oc = (float4*)out;
        oc[pid] = make_float4(cr, cg, cb, edv);
        out[W*H*4 + pid] = acc;
    }
}

extern "C" void kernel_launch(void* const* d_in, const int* in_sizes, int n_in,
                              void* d_out, int out_size) {
    const float* means3d = (const float*)d_in[0];
    const float* quats   = (const float*)d_in[1];
    const float* scales  = (const float*)d_in[2];
    const float* opac    = (const float*)d_in[3];
    const float* sh      = (const float*)d_in[4];
    const float* c2w     = (const float*)d_in[5];
    const float* Km      = (const float*)d_in[6];
    int N = in_sizes[0] / 3;

    // out = (1,H,W,4) colors ++ (1,H,W,1) alphas -> 5 floats per pixel; square image
    int P = out_size / 5;
    int W = (int)(sqrtf((float)P) + 0.5f);
    int H = W;

    preprocess_kernel<<<1, 1024>>>(means3d, quats, scales, opac, sh, c2w, Km, N);
    dim3 grid((W + TW - 1)/TW, (H + TH - 1)/TH);
    rasterize_kernel<<<grid, TW*TH>>>((float*)d_out, N, W, H);
}

// round 5
// speedup vs baseline: 2.1049x; 2.1049x over previous
#include <cuda_runtime.h>
#include <math.h>

#define SH_C0 0.28209479177387814f
#define SH_C1 0.4886025119029199f
#define NEAR_P 0.01f
#define FAR_P 1e10f
#define LOWPASS 0.3f
#define ALPHA_MIN (1.0f/255.0f)
#define ALPHA_MAX 0.999f

#define NMAX 2048
#define FULLMASK 0xffffffffu

// sorted SoA params
__device__ float4 g_a[NMAX];  // mean2d.x, mean2d.y, conA, conB
__device__ float4 g_b[NMAX];  // conC, opacity, depth, 0
__device__ float4 g_c[NMAX];  // colR, colG, colB, 0
// unsorted staging
__device__ float4 p_a[NMAX], p_b[NMAX], p_c[NMAX];
__device__ float  g_key[NMAX];

__global__ __launch_bounds__(256)
void preprocess_kernel(const float* __restrict__ means3d,
                       const float* __restrict__ quats,
                       const float* __restrict__ scales,
                       const float* __restrict__ opac,
                       const float* __restrict__ sh,
                       const float* __restrict__ c2w,
                       const float* __restrict__ Km,
                       int N)
{
    int i = blockIdx.x * blockDim.x + threadIdx.x;
    if (i >= N) return;

    // viewmat = inverse of rigid camtoworld: Rw = R^T, tw = -R^T t
    float R00=c2w[0], R01=c2w[1], R02=c2w[2],  t0=c2w[3];
    float R10=c2w[4], R11=c2w[5], R12=c2w[6],  t1=c2w[7];
    float R20=c2w[8], R21=c2w[9], R22=c2w[10], t2=c2w[11];
    float Rw00=R00, Rw01=R10, Rw02=R20;
    float Rw10=R01, Rw11=R11, Rw12=R21;
    float Rw20=R02, Rw21=R12, Rw22=R22;
    float tw0 = -(Rw00*t0 + Rw01*t1 + Rw02*t2);
    float tw1 = -(Rw10*t0 + Rw11*t1 + Rw12*t2);
    float tw2 = -(Rw20*t0 + Rw21*t1 + Rw22*t2);
    float fx=Km[0], cx=Km[2], fy=Km[4], cy=Km[5];

    float m0 = means3d[3*i+0], m1 = means3d[3*i+1], m2 = means3d[3*i+2];
    float xc = Rw00*m0 + Rw01*m1 + Rw02*m2 + tw0;
    float yc = Rw10*m0 + Rw11*m1 + Rw12*m2 + tw1;
    float zc = Rw20*m0 + Rw21*m1 + Rw22*m2 + tw2;
    bool valid = (zc > NEAR_P) && (zc < FAR_P);
    float zs = valid ? zc : 1.0f;
    float iz = 1.0f / zs;
    float m2x = fx*xc*iz + cx;
    float m2y = fy*yc*iz + cy;

    float qw=quats[4*i+0], qx=quats[4*i+1], qy=quats[4*i+2], qz=quats[4*i+3];
    float qn = rsqrtf(qw*qw + qx*qx + qy*qy + qz*qz);
    qw*=qn; qx*=qn; qy*=qn; qz*=qn;
    float Rg[3][3];
    Rg[0][0]=1.f-2.f*(qy*qy+qz*qz); Rg[0][1]=2.f*(qx*qy-qw*qz); Rg[0][2]=2.f*(qx*qz+qw*qy);
    Rg[1][0]=2.f*(qx*qy+qw*qz); Rg[1][1]=1.f-2.f*(qx*qx+qz*qz); Rg[1][2]=2.f*(qy*qz-qw*qx);
    Rg[2][0]=2.f*(qx*qz-qw*qy); Rg[2][1]=2.f*(qy*qz+qw*qx); Rg[2][2]=1.f-2.f*(qx*qx+qy*qy);

    float s0=scales[3*i+0], s1=scales[3*i+1], s2=scales[3*i+2];
    float ss0=s0*s0, ss1=s1*s1, ss2=s2*s2;

    float C3[3][3];
    #pragma unroll
    for (int r=0;r<3;r++)
        #pragma unroll
        for (int c=0;c<3;c++)
            C3[r][c] = Rg[r][0]*Rg[c][0]*ss0 + Rg[r][1]*Rg[c][1]*ss1 + Rg[r][2]*Rg[c][2]*ss2;

    float Rwm[3][3] = {{Rw00,Rw01,Rw02},{Rw10,Rw11,Rw12},{Rw20,Rw21,Rw22}};
    float T1[3][3], Cc[3][3];
    #pragma unroll
    for (int r=0;r<3;r++)
        #pragma unroll
        for (int c=0;c<3;c++)
            T1[r][c] = Rwm[r][0]*C3[0][c] + Rwm[r][1]*C3[1][c] + Rwm[r][2]*C3[2][c];
    #pragma unroll
    for (int r=0;r<3;r++)
        #pragma unroll
        for (int c=0;c<3;c++)
            Cc[r][c] = T1[r][0]*Rwm[c][0] + T1[r][1]*Rwm[c][1] + T1[r][2]*Rwm[c][2];

    float J00 = fx*iz,  J02 = -fx*xc*iz*iz;
    float J11 = fy*iz,  J12 = -fy*yc*iz*iz;
    float v00 = J00*Cc[0][0] + J02*Cc[2][0];
    float v01 = J00*Cc[0][1] + J02*Cc[2][1];
    float v02 = J00*Cc[0][2] + J02*Cc[2][2];
    float v11 = J11*Cc[1][1] + J12*Cc[2][1];
    float v12 = J11*Cc[1][2] + J12*Cc[2][2];
    float c00 = v00*J00 + v02*J02;
    float c01 = v01*J11 + v02*J12;
    float c11 = v11*J11 + v12*J12;

    float A = c00 + LOWPASS;
    float B = c01;
    float Cq = c11 + LOWPASS;
    float det = A*Cq - B*B;
    valid = valid && (det > 0.f);
    float dets = (det > 0.f) ? det : 1.f;
    float idet = 1.f / dets;
    float conA = Cq*idet, conB = -B*idet, conC = A*idet;

    float dx = m0 - t0, dy = m1 - t1, dz = m2 - t2;
    float dn = sqrtf(dx*dx + dy*dy + dz*dz);
    float inv = 1.f / fmaxf(dn, 1e-8f);
    dx*=inv; dy*=inv; dz*=inv;
    const float* shp = sh + 12*i;
    float colr = SH_C0*shp[0] - SH_C1*dy*shp[3] + SH_C1*dz*shp[6] - SH_C1*dx*shp[9];
    float colg = SH_C0*shp[1] - SH_C1*dy*shp[4] + SH_C1*dz*shp[7] - SH_C1*dx*shp[10];
    float colb = SH_C0*shp[2] - SH_C1*dy*shp[5] + SH_C1*dz*shp[8] - SH_C1*dx*shp[11];
    colr = fmaxf(colr + 0.5f, 0.f);
    colg = fmaxf(colg + 0.5f, 0.f);
    colb = fmaxf(colb + 0.5f, 0.f);

    float opa = 1.f / (1.f + __expf(-opac[i]));
    float op = valid ? opa : 0.f;

    p_a[i] = make_float4(m2x, m2y, conA, conB);
    p_b[i] = make_float4(conC, op, zc, 0.f);
    p_c[i] = make_float4(colr, colg, colb, 0.f);
    g_key[i] = valid ? zc : INFINITY;
}

// one warp per element: stable rank by counting, then scatter into SoA
__global__ __launch_bounds__(256)
void rank_scatter_kernel(int N)
{
    int warp = threadIdx.x >> 5;
    int lane = threadIdx.x & 31;
    int i = blockIdx.x * 8 + warp;
    if (i >= N) return;
    float ki = g_key[i];
    int cnt = 0;
    for (int j = lane; j < N; j += 32) {
        float kj = g_key[j];
        cnt += (kj < ki) || ((kj == ki) && (j < i));
    }
    int rank = __reduce_add_sync(FULLMASK, cnt);
    if (lane == 0) {
        g_a[rank] = p_a[i];
        g_b[rank] = p_b[i];
        g_c[rank] = p_c[i];
    }
}

// one warp per pixel; 32 gaussians per warp-iteration, warp-scan prefix products
#define WPB 8
__global__ __launch_bounds__(32*WPB)
void rasterize_kernel(float* __restrict__ out, int N, int W, int H)
{
    int warp = threadIdx.x >> 5;
    int lane = threadIdx.x & 31;
    int pid = blockIdx.x * WPB + warp;
    if (pid >= W*H) return;
    float pxf = (float)(pid % W) + 0.5f;
    float pyf = (float)(pid / W) + 0.5f;

    float Tt = 1.f;
    float cr = 0.f, cg = 0.f, cb = 0.f, acc = 0.f, ed = 0.f;

    for (int base = 0; base < N; base += 32) {
        int j = base + lane;
        float alpha = 0.f;
        float dep = 0.f;
        if (j < N) {
            float4 a  = g_a[j];
            float4 b4 = g_b[j];
            float ddx = pxf - a.x;
            float ddy = pyf - a.y;
            float sigma = 0.5f*(a.z*ddx*ddx + b4.x*ddy*ddy) + a.w*ddx*ddy;
            float al = fminf(b4.y * __expf(-sigma), ALPHA_MAX);
            alpha = (sigma >= 0.f && al >= ALPHA_MIN) ? al : 0.f;
            dep = b4.z;
        }
        float om = 1.f - alpha;

        // inclusive scan (product) of om across the warp
        float p = om;
        #pragma unroll
        for (int off = 1; off < 32; off <<= 1) {
            float t = __shfl_up_sync(FULLMASK, p, off);
            if (lane >= off) p *= t;
        }
        // exclusive prefix for this lane
        float excl = __shfl_up_sync(FULLMASK, p, 1);
        if (lane == 0) excl = 1.f;

        if (alpha > 0.f) {
            float w = alpha * Tt * excl;
            float4 c4 = g_c[j];
            cr  += w * c4.x;
            cg  += w * c4.y;
            cb  += w * c4.z;
            acc += w;
            ed  += w * dep;
        }

        float tot = __shfl_sync(FULLMASK, p, 31);
        Tt *= tot;
        if (Tt < 1e-5f) break;   // warp-uniform
    }

    // warp reduce the 5 accumulators
    #pragma unroll
    for (int off = 16; off > 0; off >>= 1) {
        cr  += __shfl_xor_sync(FULLMASK, cr,  off);
        cg  += __shfl_xor_sync(FULLMASK, cg,  off);
        cb  += __shfl_xor_sync(FULLMASK, cb,  off);
        acc += __shfl_xor_sync(FULLMASK, acc, off);
        ed  += __shfl_xor_sync(FULLMASK, ed,  off);
    }

    if (lane == 0) {
        float edv = ed / fmaxf(acc, 1e-10f);
        ((float4*)out)[pid] = make_float4(cr, cg, cb, edv);
        out[W*H*4 + pid] = acc;
    }
}

extern "C" void kernel_launch(void* const* d_in, const int* in_sizes, int n_in,
                              void* d_out, int out_size) {
    const float* means3d = (const float*)d_in[0];
    const float* quats   = (const float*)d_in[1];
    const float* scales  = (const float*)d_in[2];
    const float* opac    = (const float*)d_in[3];
    const float* sh      = (const float*)d_in[4];
    const float* c2w     = (const float*)d_in[5];
    const float* Km      = (const float*)d_in[6];
    int N = in_sizes[0] / 3;

    int P = out_size / 5;
    int W = (int)(sqrtf((float)P) + 0.5f);
    int H = W;

    preprocess_kernel<<<(N + 255)/256, 256>>>(means3d, quats, scales, opac, sh, c2w, Km, N);
    rank_scatter_kernel<<<(N + 7)/8, 256>>>(N);
    int npix = W * H;
    rasterize_kernel<<<(npix + WPB - 1)/WPB, 32*WPB>>>((float*)d_out, N, W, H);
}

// round 6
// speedup vs baseline: 8.3881x; 3.9851x over previous
#include <cuda_runtime.h>
#include <math.h>

#define SH_C0 0.28209479177387814f
#define SH_C1 0.4886025119029199f
#define NEAR_P 0.01f
#define FAR_P 1e10f
#define LOWPASS 0.3f
#define ALPHA_MIN (1.0f/255.0f)
#define ALPHA_MAX 0.999f

#define NMAX 2048
#define FULLMASK 0xffffffffu

// sorted SoA params
__device__ float4 g_a[NMAX];  // mean2d.x, mean2d.y, conA, conB
__device__ float4 g_b[NMAX];  // conC, opacity, depth, rx
__device__ float4 g_c[NMAX];  // colR, colG, colB, ry
// unsorted staging
__device__ float4 p_a[NMAX], p_b[NMAX], p_c[NMAX];
__device__ float  g_key[NMAX];

__global__ __launch_bounds__(128)
void preprocess_kernel(const float* __restrict__ means3d,
                       const float* __restrict__ quats,
                       const float* __restrict__ scales,
                       const float* __restrict__ opac,
                       const float* __restrict__ sh,
                       const float* __restrict__ c2w,
                       const float* __restrict__ Km,
                       int N)
{
    int i = blockIdx.x * blockDim.x + threadIdx.x;
    if (i >= N) return;

    // viewmat = inverse of rigid camtoworld: Rw = R^T, tw = -R^T t
    float R00=c2w[0], R01=c2w[1], R02=c2w[2],  t0=c2w[3];
    float R10=c2w[4], R11=c2w[5], R12=c2w[6],  t1=c2w[7];
    float R20=c2w[8], R21=c2w[9], R22=c2w[10], t2=c2w[11];
    float Rw00=R00, Rw01=R10, Rw02=R20;
    float Rw10=R01, Rw11=R11, Rw12=R21;
    float Rw20=R02, Rw21=R12, Rw22=R22;
    float tw0 = -(Rw00*t0 + Rw01*t1 + Rw02*t2);
    float tw1 = -(Rw10*t0 + Rw11*t1 + Rw12*t2);
    float tw2 = -(Rw20*t0 + Rw21*t1 + Rw22*t2);
    float fx=Km[0], cx=Km[2], fy=Km[4], cy=Km[5];

    float m0 = means3d[3*i+0], m1 = means3d[3*i+1], m2 = means3d[3*i+2];
    float xc = Rw00*m0 + Rw01*m1 + Rw02*m2 + tw0;
    float yc = Rw10*m0 + Rw11*m1 + Rw12*m2 + tw1;
    float zc = Rw20*m0 + Rw21*m1 + Rw22*m2 + tw2;
    bool valid = (zc > NEAR_P) && (zc < FAR_P);
    float zs = valid ? zc : 1.0f;
    float iz = 1.0f / zs;
    float m2x = fx*xc*iz + cx;
    float m2y = fy*yc*iz + cy;

    float4 q4 = ((const float4*)quats)[i];
    float qw=q4.x, qx=q4.y, qy=q4.z, qz=q4.w;
    float qn = rsqrtf(qw*qw + qx*qx + qy*qy + qz*qz);
    qw*=qn; qx*=qn; qy*=qn; qz*=qn;
    float Rg[3][3];
    Rg[0][0]=1.f-2.f*(qy*qy+qz*qz); Rg[0][1]=2.f*(qx*qy-qw*qz); Rg[0][2]=2.f*(qx*qz+qw*qy);
    Rg[1][0]=2.f*(qx*qy+qw*qz); Rg[1][1]=1.f-2.f*(qx*qx+qz*qz); Rg[1][2]=2.f*(qy*qz-qw*qx);
    Rg[2][0]=2.f*(qx*qz-qw*qy); Rg[2][1]=2.f*(qy*qz+qw*qx); Rg[2][2]=1.f-2.f*(qx*qx+qy*qy);

    float s0=scales[3*i+0], s1=scales[3*i+1], s2=scales[3*i+2];
    float ss0=s0*s0, ss1=s1*s1, ss2=s2*s2;

    float C3[3][3];
    #pragma unroll
    for (int r=0;r<3;r++)
        #pragma unroll
        for (int c=0;c<3;c++)
            C3[r][c] = Rg[r][0]*Rg[c][0]*ss0 + Rg[r][1]*Rg[c][1]*ss1 + Rg[r][2]*Rg[c][2]*ss2;

    float Rwm[3][3] = {{Rw00,Rw01,Rw02},{Rw10,Rw11,Rw12},{Rw20,Rw21,Rw22}};
    float T1[3][3], Cc[3][3];
    #pragma unroll
    for (int r=0;r<3;r++)
        #pragma unroll
        for (int c=0;c<3;c++)
            T1[r][c] = Rwm[r][0]*C3[0][c] + Rwm[r][1]*C3[1][c] + Rwm[r][2]*C3[2][c];
    #pragma unroll
    for (int r=0;r<3;r++)
        #pragma unroll
        for (int c=0;c<3;c++)
            Cc[r][c] = T1[r][0]*Rwm[c][0] + T1[r][1]*Rwm[c][1] + T1[r][2]*Rwm[c][2];

    float J00 = fx*iz,  J02 = -fx*xc*iz*iz;
    float J11 = fy*iz,  J12 = -fy*yc*iz*iz;
    float v00 = J00*Cc[0][0] + J02*Cc[2][0];
    float v01 = J00*Cc[0][1] + J02*Cc[2][1];
    float v02 = J00*Cc[0][2] + J02*Cc[2][2];
    float v11 = J11*Cc[1][1] + J12*Cc[2][1];
    float v12 = J11*Cc[1][2] + J12*Cc[2][2];
    float c00 = v00*J00 + v02*J02;
    float c01 = v01*J11 + v02*J12;
    float c11 = v11*J11 + v12*J12;

    float A = c00 + LOWPASS;
    float B = c01;
    float Cq = c11 + LOWPASS;
    float det = A*Cq - B*B;
    valid = valid && (det > 0.f);
    float dets = (det > 0.f) ? det : 1.f;
    float idet = 1.f / dets;
    float conA = Cq*idet, conB = -B*idet, conC = A*idet;

    float dx = m0 - t0, dy = m1 - t1, dz = m2 - t2;
    float dn = sqrtf(dx*dx + dy*dy + dz*dz);
    float inv = 1.f / fmaxf(dn, 1e-8f);
    dx*=inv; dy*=inv; dz*=inv;
    const float* shp = sh + 12*i;
    float colr = SH_C0*shp[0] - SH_C1*dy*shp[3] + SH_C1*dz*shp[6] - SH_C1*dx*shp[9];
    float colg = SH_C0*shp[1] - SH_C1*dy*shp[4] + SH_C1*dz*shp[7] - SH_C1*dx*shp[10];
    float colb = SH_C0*shp[2] - SH_C1*dy*shp[5] + SH_C1*dz*shp[8] - SH_C1*dx*shp[11];
    colr = fmaxf(colr + 0.5f, 0.f);
    colg = fmaxf(colg + 0.5f, 0.f);
    colb = fmaxf(colb + 0.5f, 0.f);

    float opa = 1.f / (1.f + __expf(-opac[i]));
    float op = valid ? opa : 0.f;

    // footprint: alpha >= 1/255 requires sigma <= tau = ln(255*op).
    // ellipse {0.5 d^T Q d <= tau} has bbox half-widths sqrt(2 tau Sigma_xx/yy),
    // Sigma = cov2d + lowpass = [[A,B],[B,Cq]].  conservative-exact.
    float rx = 0.f, ry = 0.f;
    float t255 = op * 255.f;
    if (valid && t255 > 1.f) {
        float tau = logf(t255);
        rx = sqrtf(2.f * tau * A);
        ry = sqrtf(2.f * tau * Cq);
    } else {
        op = 0.f;  // never contributes anywhere
    }

    p_a[i] = make_float4(m2x, m2y, conA, conB);
    p_b[i] = make_float4(conC, op, zc, rx);
    p_c[i] = make_float4(colr, colg, colb, ry);
    g_key[i] = valid ? zc : INFINITY;
}

// one warp per element: stable rank by counting, then scatter into SoA
__global__ __launch_bounds__(256)
void rank_scatter_kernel(int N)
{
    int warp = threadIdx.x >> 5;
    int lane = threadIdx.x & 31;
    int i = blockIdx.x * 8 + warp;
    if (i >= N) return;
    float ki = g_key[i];
    int cnt = 0;
    for (int j = lane; j < N; j += 32) {
        float kj = g_key[j];
        cnt += (kj < ki) || ((kj == ki) && (j < i));
    }
    int rank = __reduce_add_sync(FULLMASK, cnt);
    if (lane == 0) {
        g_a[rank] = p_a[i];
        g_b[rank] = p_b[i];
        g_c[rank] = p_c[i];
    }
}

// 16x16 pixel tile per block, 256 threads (one per pixel).
// Per 256-gaussian chunk: ordered ballot-compaction of tile-intersecting
// gaussians into smem, then serial per-pixel front-to-back composite.
#define TS 16
#define NW 8
__global__ __launch_bounds__(TS*TS)
void rasterize_kernel(float* __restrict__ out, int N, int W, int H)
{
    __shared__ float4 sa[TS*TS], sb[TS*TS], sc[TS*TS];
    __shared__ int s_wcnt[NW];

    int tid  = threadIdx.x;
    int lane = tid & 31;
    int warp = tid >> 5;
    int tx = tid & (TS-1);
    int ty = tid >> 4;
    int x = blockIdx.x*TS + tx;
    int y = blockIdx.y*TS + ty;
    float pxf = x + 0.5f, pyf = y + 0.5f;

    // tile pixel-center bounds
    float tx0 = blockIdx.x*TS + 0.5f, tx1 = tx0 + (TS-1);
    float ty0 = blockIdx.y*TS + 0.5f, ty1 = ty0 + (TS-1);

    float Tt = 1.f, cr = 0.f, cg = 0.f, cb = 0.f, acc = 0.f, ed = 0.f;

    for (int base = 0; base < N; base += TS*TS) {
        int j = base + tid;
        bool hit = false;
        float4 a4, b4, c4;
        if (j < N) {
            a4 = g_a[j]; b4 = g_b[j]; c4 = g_c[j];
            hit = (b4.y > 0.f)
               && (a4.x + b4.w >= tx0) && (a4.x - b4.w <= tx1)
               && (a4.y + c4.w >= ty0) && (a4.y - c4.w <= ty1);
        }
        unsigned bm = __ballot_sync(FULLMASK, hit);
        if (lane == 0) s_wcnt[warp] = __popc(bm);
        __syncthreads();
        int off = 0, total = 0;
        #pragma unroll
        for (int w2 = 0; w2 < NW; w2++) {
            int v = s_wcnt[w2];
            total += v;
            if (w2 < warp) off += v;
        }
        off += __popc(bm & ((1u << lane) - 1u));
        if (hit) { sa[off] = a4; sb[off] = b4; sc[off] = c4; }
        __syncthreads();

        if (Tt >= 1e-5f) {
            for (int k = 0; k < total; k++) {
                float4 a = sa[k];
                float ddx = pxf - a.x;
                float ddy = pyf - a.y;
                float4 bq = sb[k];
                float sigma = 0.5f*(a.z*ddx*ddx + bq.x*ddy*ddy) + a.w*ddx*ddy;
                float alpha = fminf(bq.y * __expf(-sigma), ALPHA_MAX);
                if (sigma >= 0.f && alpha >= ALPHA_MIN) {
                    float w = alpha * Tt;
                    float4 cq = sc[k];
                    cr += w*cq.x; cg += w*cq.y; cb += w*cq.z;
                    acc += w; ed += w*bq.z;
                    Tt *= (1.f - alpha);
                    if (Tt < 1e-5f) break;
                }
            }
        }
        if (__syncthreads_and(Tt < 1e-5f)) break;
    }

    if (x < W && y < H) {
        int pid = y*W + x;
        float edv = ed / fmaxf(acc, 1e-10f);
        ((float4*)out)[pid] = make_float4(cr, cg, cb, edv);
        out[W*H*4 + pid] = acc;
    }
}

extern "C" void kernel_launch(void* const* d_in, const int* in_sizes, int n_in,
                              void* d_out, int out_size) {
    const float* means3d = (const float*)d_in[0];
    const float* quats   = (const float*)d_in[1];
    const float* scales  = (const float*)d_in[2];
    const float* opac    = (const float*)d_in[3];
    const float* sh      = (const float*)d_in[4];
    const float* c2w     = (const float*)d_in[5];
    const float* Km      = (const float*)d_in[6];
    int N = in_sizes[0] / 3;

    int P = out_size / 5;
    int W = (int)(sqrtf((float)P) + 0.5f);
    int H = W;

    preprocess_kernel<<<(N + 127)/128, 128>>>(means3d, quats, scales, opac, sh, c2w, Km, N);
    rank_scatter_kernel<<<(N + 7)/8, 256>>>(N);
    dim3 grid((W + TS - 1)/TS, (H + TS - 1)/TS);
    rasterize_kernel<<<grid, TS*TS>>>((float*)d_out, N, W, H);
}